// round 1
// baseline (speedup 1.0000x reference)
#include <cuda_runtime.h>
#include <math.h>

#define D_IN  1024
#define H1    128
#define QD    32      // HEADS * K_DIM
#define NKEYS 256
#define KNN   8
#define HALF  8
#define MAXT  8192

// Scratch (static __device__ — no allocation allowed)
__device__ float g_q[MAXT * QD];
__device__ int   g_idx[MAXT * 16];
__device__ float g_w[MAXT * 16];

// ---------------------------------------------------------------------------
// Kernel A: fused  h = relu(x @ W1^T + b1);  q = h @ W2^T + b2
// BM=64 tokens per block, full N=128, BK=16. 256 threads, 8x4 microtile.
// Phase 2 (tiny GEMM2) reuses smem for the H tile + transposed W2.
// ---------------------------------------------------------------------------
__global__ __launch_bounds__(256, 1) void mlp_kernel(
    const float* __restrict__ x,  const float* __restrict__ W1,
    const float* __restrict__ b1, const float* __restrict__ W2,
    const float* __restrict__ b2, float* __restrict__ qout)
{
    extern __shared__ float smem[];
    float* Xs = smem;             // [64][16]   phase 1
    float* Ws = smem + 64 * 16;   // [16][128]  phase 1 (k-major)
    float* Hs  = smem;            // [64][130]  phase 2 (padded)
    float* W2T = smem + 64 * 130; // [128][32]  phase 2 (k-major)

    const int tid = threadIdx.x;
    const int block_row = blockIdx.x * 64;

    const int tcol = (tid & 31) * 4;   // 0..124
    const int trow = (tid >> 5) * 8;   // 0..56

    float acc[8][4];
#pragma unroll
    for (int r = 0; r < 8; r++)
#pragma unroll
        for (int c = 0; c < 4; c++) acc[r][c] = 0.f;

    const float* xBase = x + (size_t)block_row * D_IN;
    const int lr = tid >> 2;          // 0..63
    const int lk = (tid & 3) * 4;     // 0,4,8,12

    for (int k0 = 0; k0 < D_IN; k0 += 16) {
        // --- load X tile: 64x16 floats, one float4 per thread
        float4 xv = *(const float4*)(xBase + (size_t)lr * D_IN + k0 + lk);
        // --- load W1 tile (2 float4 per thread), scatter k-major
        int j0 = tid, j1 = tid + 256;
        int n0 = j0 >> 2, kq0 = (j0 & 3) * 4;
        int n1 = j1 >> 2, kq1 = (j1 & 3) * 4;
        float4 wv0 = *(const float4*)(W1 + (size_t)n0 * D_IN + k0 + kq0);
        float4 wv1 = *(const float4*)(W1 + (size_t)n1 * D_IN + k0 + kq1);

        *(float4*)&Xs[lr * 16 + lk] = xv;
        Ws[(kq0 + 0) * H1 + n0] = wv0.x;
        Ws[(kq0 + 1) * H1 + n0] = wv0.y;
        Ws[(kq0 + 2) * H1 + n0] = wv0.z;
        Ws[(kq0 + 3) * H1 + n0] = wv0.w;
        Ws[(kq1 + 0) * H1 + n1] = wv1.x;
        Ws[(kq1 + 1) * H1 + n1] = wv1.y;
        Ws[(kq1 + 2) * H1 + n1] = wv1.z;
        Ws[(kq1 + 3) * H1 + n1] = wv1.w;
        __syncthreads();

#pragma unroll
        for (int k = 0; k < 16; k++) {
            float4 w4 = *(const float4*)&Ws[k * H1 + tcol];
            float xr[8];
#pragma unroll
            for (int r = 0; r < 8; r++) xr[r] = Xs[(trow + r) * 16 + k];
#pragma unroll
            for (int r = 0; r < 8; r++) {
                acc[r][0] = fmaf(xr[r], w4.x, acc[r][0]);
                acc[r][1] = fmaf(xr[r], w4.y, acc[r][1]);
                acc[r][2] = fmaf(xr[r], w4.z, acc[r][2]);
                acc[r][3] = fmaf(xr[r], w4.w, acc[r][3]);
            }
        }
        __syncthreads();
    }

    // --- write H tile (relu + b1)
    float bb[4];
#pragma unroll
    for (int c = 0; c < 4; c++) bb[c] = b1[tcol + c];
#pragma unroll
    for (int r = 0; r < 8; r++)
#pragma unroll
        for (int c = 0; c < 4; c++)
            Hs[(trow + r) * 130 + tcol + c] = fmaxf(acc[r][c] + bb[c], 0.f);

    // --- load W2 transposed (k-major)  [128][32]
    for (int i = tid; i < 32 * 32; i += 256) {   // 1024 float4s of W2
        int c  = i >> 5;            // 0..31
        int kq = (i & 31) * 4;      // 0..124
        float4 v = *(const float4*)(W2 + (size_t)c * H1 + kq);
        W2T[(kq + 0) * 32 + c] = v.x;
        W2T[(kq + 1) * 32 + c] = v.y;
        W2T[(kq + 2) * 32 + c] = v.z;
        W2T[(kq + 3) * 32 + c] = v.w;
    }
    __syncthreads();

    // --- GEMM2: each thread does one H row (rr), 8 q-cols (cb..cb+7)
    const int rr = tid >> 2;
    const int cb = (tid & 3) * 8;
    float a2[8];
#pragma unroll
    for (int c = 0; c < 8; c++) a2[c] = 0.f;
#pragma unroll 4
    for (int k = 0; k < H1; k++) {
        float hv = Hs[rr * 130 + k];
        float4 w0 = *(const float4*)&W2T[k * 32 + cb];
        float4 w1 = *(const float4*)&W2T[k * 32 + cb + 4];
        a2[0] = fmaf(hv, w0.x, a2[0]);
        a2[1] = fmaf(hv, w0.y, a2[1]);
        a2[2] = fmaf(hv, w0.z, a2[2]);
        a2[3] = fmaf(hv, w0.w, a2[3]);
        a2[4] = fmaf(hv, w1.x, a2[4]);
        a2[5] = fmaf(hv, w1.y, a2[5]);
        a2[6] = fmaf(hv, w1.z, a2[6]);
        a2[7] = fmaf(hv, w1.w, a2[7]);
    }
#pragma unroll
    for (int c = 0; c < 8; c++)
        qout[(size_t)(block_row + rr) * QD + cb + c] = a2[c] + b2[cb + c];
}

// ---------------------------------------------------------------------------
// Kernel B: per (token, head) warp — scores, two top-8s, combo top-8, softmax
// ---------------------------------------------------------------------------
__device__ __forceinline__ void warp_top8(float v[8], int base,
                                          float outs[8], int outi[8])
{
#pragma unroll
    for (int sel = 0; sel < 8; sel++) {
        // local argmax (ties -> lowest local index)
        float m = v[0]; int mi = 0;
#pragma unroll
        for (int i = 1; i < 8; i++)
            if (v[i] > m) { m = v[i]; mi = i; }
        float bm = m; int bi = base + mi;
#pragma unroll
        for (int off = 16; off; off >>= 1) {
            float om = __shfl_xor_sync(0xffffffffu, bm, off);
            int   oi = __shfl_xor_sync(0xffffffffu, bi, off);
            if (om > bm || (om == bm && oi < bi)) { bm = om; bi = oi; }
        }
        outs[sel] = bm; outi[sel] = bi;
        if (bi >= base && bi < base + 8) v[bi - base] = -INFINITY;
    }
}

__global__ __launch_bounds__(256) void topk_kernel(
    const float* __restrict__ q, const float* __restrict__ keys,
    int* __restrict__ oidx, float* __restrict__ ow, int T)
{
    int gw = (blockIdx.x * 256 + threadIdx.x) >> 5;
    if (gw >= T * 2) return;
    int lane = threadIdx.x & 31;
    int t = gw >> 1, h = gw & 1;

    const float* qp = q + (size_t)t * QD + h * 16;
    float q1[HALF], q2[HALF];
#pragma unroll
    for (int c = 0; c < HALF; c++) { q1[c] = qp[c]; q2[c] = qp[HALF + c]; }

    // scores for 8 keys per lane, both halves
    float s1[8], s2[8];
    {
        const float* k1 = keys + ((size_t)(h * 2 + 0) * NKEYS + lane * 8) * HALF;
        const float* k2 = keys + ((size_t)(h * 2 + 1) * NKEYS + lane * 8) * HALF;
#pragma unroll
        for (int j = 0; j < 8; j++) {
            float a = 0.f, b = 0.f;
#pragma unroll
            for (int c = 0; c < HALF; c++) {
                a = fmaf(q1[c], k1[j * HALF + c], a);
                b = fmaf(q2[c], k2[j * HALF + c], b);
            }
            s1[j] = a; s2[j] = b;
        }
    }

    float sc1[8], sc2[8]; int i1[8], i2[8];
    warp_top8(s1, lane * 8, sc1, i1);
    warp_top8(s2, lane * 8, sc2, i2);

    // 64 combos: p = lane (slot0) and lane+32 (slot1); flattened idx = p = i*8+j
    float cv0 = sc1[lane >> 3]        + sc2[lane & 7];
    float cv1 = sc1[(lane + 32) >> 3] + sc2[(lane + 32) & 7];

    float fsc[8]; int fp[8];
#pragma unroll
    for (int sel = 0; sel < 8; sel++) {
        float m; int mi;
        if (cv0 >= cv1) { m = cv0; mi = lane; } else { m = cv1; mi = lane + 32; }
        float bm = m; int bi = mi;
#pragma unroll
        for (int off = 16; off; off >>= 1) {
            float om = __shfl_xor_sync(0xffffffffu, bm, off);
            int   oi = __shfl_xor_sync(0xffffffffu, bi, off);
            if (om > bm || (om == bm && oi < bi)) { bm = om; bi = oi; }
        }
        fsc[sel] = bm; fp[sel] = bi;
        if (bi == lane)           cv0 = -INFINITY;
        else if (bi == lane + 32) cv1 = -INFINITY;
    }

    // softmax (fsc is descending; fsc[0] is the max)
    float mx = fsc[0];
    float e[8], sum = 0.f;
#pragma unroll
    for (int k = 0; k < 8; k++) { e[k] = expf(fsc[k] - mx); sum += e[k]; }
    float inv = 1.f / sum;

    if (lane < 8) {
        int p = fp[lane];
        oidx[(size_t)gw * 8 + lane] = i1[p >> 3] * NKEYS + i2[p & 7];
        ow  [(size_t)gw * 8 + lane] = e[lane] * inv;
    }
}

// ---------------------------------------------------------------------------
// Kernel C: weighted gather  out[t] = sum_k w[t][k] * values[idx[t][k]]
// ---------------------------------------------------------------------------
__global__ __launch_bounds__(256) void gather_kernel(
    const int* __restrict__ oidx, const float* __restrict__ ow,
    const float* __restrict__ values, float* __restrict__ out)
{
    const int t = blockIdx.x;
    const int tid = threadIdx.x;
    __shared__ int   sidx[16];
    __shared__ float sw[16];
    if (tid < 16) {
        sidx[tid] = oidx[(size_t)t * 16 + tid];
        sw[tid]   = ow  [(size_t)t * 16 + tid];
    }
    __syncthreads();

    float4 acc = make_float4(0.f, 0.f, 0.f, 0.f);
#pragma unroll
    for (int k = 0; k < 16; k++) {
        const float4* vp = (const float4*)(values + (size_t)sidx[k] * D_IN) + tid;
        float4 v = *vp;
        float w = sw[k];
        acc.x = fmaf(w, v.x, acc.x);
        acc.y = fmaf(w, v.y, acc.y);
        acc.z = fmaf(w, v.z, acc.z);
        acc.w = fmaf(w, v.w, acc.w);
    }
    ((float4*)out)[(size_t)t * 256 + tid] = acc;
}

// ---------------------------------------------------------------------------
extern "C" void kernel_launch(void* const* d_in, const int* in_sizes, int n_in,
                              void* d_out, int out_size)
{
    const float* x      = (const float*)d_in[0];
    const float* W1     = (const float*)d_in[1];
    const float* b1     = (const float*)d_in[2];
    const float* W2     = (const float*)d_in[3];
    const float* b2     = (const float*)d_in[4];
    const float* keys   = (const float*)d_in[5];
    const float* values = (const float*)d_in[6];
    float* out = (float*)d_out;

    const int T = in_sizes[0] / D_IN;   // 8192

    float* qbuf;  cudaGetSymbolAddress((void**)&qbuf, g_q);
    int*   idxb;  cudaGetSymbolAddress((void**)&idxb, g_idx);
    float* wb;    cudaGetSymbolAddress((void**)&wb,   g_w);

    const int smemA = (64 * 130 + 128 * 32) * (int)sizeof(float);  // 49664 B
    cudaFuncSetAttribute(mlp_kernel, cudaFuncAttributeMaxDynamicSharedMemorySize, smemA);

    mlp_kernel<<<T / 64, 256, smemA>>>(x, W1, b1, W2, b2, qbuf);
    topk_kernel<<<(T * 2 * 32 + 255) / 256, 256>>>(qbuf, keys, idxb, wb, T);
    gather_kernel<<<T, 256>>>(idxb, wb, values, out);
}

// round 2
// speedup vs baseline: 1.0987x; 1.0987x over previous
#include <cuda_runtime.h>
#include <math.h>

#define D_IN  1024
#define H1    128
#define QD    32      // HEADS * K_DIM
#define NKEYS 256
#define KNN   8
#define HALF  8
#define MAXT  8192

// Scratch (static __device__ — no allocation allowed)
__device__ float g_q[MAXT * QD];
__device__ int   g_idx[MAXT * 16];
__device__ float g_w[MAXT * 16];

// ---------------------------------------------------------------------------
// Kernel A: fused  h = relu(x @ W1^T + b1);  q = h @ W2^T + b2
// ---------------------------------------------------------------------------
__global__ __launch_bounds__(256, 1) void mlp_kernel(
    const float* __restrict__ x,  const float* __restrict__ W1,
    const float* __restrict__ b1, const float* __restrict__ W2,
    const float* __restrict__ b2, float* __restrict__ qout)
{
    extern __shared__ float smem[];
    float* Xs = smem;             // [64][16]   phase 1
    float* Ws = smem + 64 * 16;   // [16][128]  phase 1 (k-major)
    float* Hs  = smem;            // [64][130]  phase 2 (padded)
    float* W2T = smem + 64 * 130; // [128][32]  phase 2 (k-major)

    const int tid = threadIdx.x;
    const int block_row = blockIdx.x * 64;

    const int tcol = (tid & 31) * 4;   // 0..124
    const int trow = (tid >> 5) * 8;   // 0..56

    float acc[8][4];
#pragma unroll
    for (int r = 0; r < 8; r++)
#pragma unroll
        for (int c = 0; c < 4; c++) acc[r][c] = 0.f;

    const float* xBase = x + (size_t)block_row * D_IN;
    const int lr = tid >> 2;          // 0..63
    const int lk = (tid & 3) * 4;     // 0,4,8,12

    for (int k0 = 0; k0 < D_IN; k0 += 16) {
        float4 xv = *(const float4*)(xBase + (size_t)lr * D_IN + k0 + lk);
        int j0 = tid, j1 = tid + 256;
        int n0 = j0 >> 2, kq0 = (j0 & 3) * 4;
        int n1 = j1 >> 2, kq1 = (j1 & 3) * 4;
        float4 wv0 = *(const float4*)(W1 + (size_t)n0 * D_IN + k0 + kq0);
        float4 wv1 = *(const float4*)(W1 + (size_t)n1 * D_IN + k0 + kq1);

        *(float4*)&Xs[lr * 16 + lk] = xv;
        Ws[(kq0 + 0) * H1 + n0] = wv0.x;
        Ws[(kq0 + 1) * H1 + n0] = wv0.y;
        Ws[(kq0 + 2) * H1 + n0] = wv0.z;
        Ws[(kq0 + 3) * H1 + n0] = wv0.w;
        Ws[(kq1 + 0) * H1 + n1] = wv1.x;
        Ws[(kq1 + 1) * H1 + n1] = wv1.y;
        Ws[(kq1 + 2) * H1 + n1] = wv1.z;
        Ws[(kq1 + 3) * H1 + n1] = wv1.w;
        __syncthreads();

#pragma unroll
        for (int k = 0; k < 16; k++) {
            float4 w4 = *(const float4*)&Ws[k * H1 + tcol];
            float xr[8];
#pragma unroll
            for (int r = 0; r < 8; r++) xr[r] = Xs[(trow + r) * 16 + k];
#pragma unroll
            for (int r = 0; r < 8; r++) {
                acc[r][0] = fmaf(xr[r], w4.x, acc[r][0]);
                acc[r][1] = fmaf(xr[r], w4.y, acc[r][1]);
                acc[r][2] = fmaf(xr[r], w4.z, acc[r][2]);
                acc[r][3] = fmaf(xr[r], w4.w, acc[r][3]);
            }
        }
        __syncthreads();
    }

    float bb[4];
#pragma unroll
    for (int c = 0; c < 4; c++) bb[c] = b1[tcol + c];
#pragma unroll
    for (int r = 0; r < 8; r++)
#pragma unroll
        for (int c = 0; c < 4; c++)
            Hs[(trow + r) * 130 + tcol + c] = fmaxf(acc[r][c] + bb[c], 0.f);

    for (int i = tid; i < 32 * 32; i += 256) {
        int c  = i >> 5;
        int kq = (i & 31) * 4;
        float4 v = *(const float4*)(W2 + (size_t)c * H1 + kq);
        W2T[(kq + 0) * 32 + c] = v.x;
        W2T[(kq + 1) * 32 + c] = v.y;
        W2T[(kq + 2) * 32 + c] = v.z;
        W2T[(kq + 3) * 32 + c] = v.w;
    }
    __syncthreads();

    const int rr = tid >> 2;
    const int cb = (tid & 3) * 8;
    float a2[8];
#pragma unroll
    for (int c = 0; c < 8; c++) a2[c] = 0.f;
#pragma unroll 4
    for (int k = 0; k < H1; k++) {
        float hv = Hs[rr * 130 + k];
        float4 w0 = *(const float4*)&W2T[k * 32 + cb];
        float4 w1 = *(const float4*)&W2T[k * 32 + cb + 4];
        a2[0] = fmaf(hv, w0.x, a2[0]);
        a2[1] = fmaf(hv, w0.y, a2[1]);
        a2[2] = fmaf(hv, w0.z, a2[2]);
        a2[3] = fmaf(hv, w0.w, a2[3]);
        a2[4] = fmaf(hv, w1.x, a2[4]);
        a2[5] = fmaf(hv, w1.y, a2[5]);
        a2[6] = fmaf(hv, w1.z, a2[6]);
        a2[7] = fmaf(hv, w1.w, a2[7]);
    }
#pragma unroll
    for (int c = 0; c < 8; c++)
        qout[(size_t)(block_row + rr) * QD + cb + c] = a2[c] + b2[cb + c];
}

// ---------------------------------------------------------------------------
// Kernel B (rewritten): NO dynamic register-array indexing anywhere.
// Selection results live as scalars on lane `sel`; cross-lane access via shfl.
// ---------------------------------------------------------------------------
#define FULLMASK 0xffffffffu

__global__ __launch_bounds__(256) void topk_kernel(
    const float* __restrict__ q, const float* __restrict__ keys,
    int* __restrict__ oidx, float* __restrict__ ow, int T)
{
    int gw = (blockIdx.x * 256 + threadIdx.x) >> 5;
    if (gw >= T * 2) return;
    const int lane = threadIdx.x & 31;
    const int t = gw >> 1, h = gw & 1;

    const float* qp = q + (size_t)t * QD + h * 16;
    float q1[HALF], q2[HALF];
#pragma unroll
    for (int c = 0; c < HALF; c++) { q1[c] = qp[c]; q2[c] = qp[HALF + c]; }

    // scores: 8 keys per lane, each half (static indexing only)
    float s1[8], s2[8];
    {
        const float* k1 = keys + ((size_t)(h * 2 + 0) * NKEYS + lane * 8) * HALF;
        const float* k2 = keys + ((size_t)(h * 2 + 1) * NKEYS + lane * 8) * HALF;
#pragma unroll
        for (int j = 0; j < 8; j++) {
            float a = 0.f, b = 0.f;
#pragma unroll
            for (int c = 0; c < HALF; c++) {
                a = fmaf(q1[c], k1[j * HALF + c], a);
                b = fmaf(q2[c], k2[j * HALF + c], b);
            }
            s1[j] = a; s2[j] = b;
        }
    }

    // top-8 of each half. Result for rank `sel` kept as scalars on lane==sel.
    float my_sc1 = 0.f, my_sc2 = 0.f;
    int   my_i1  = 0,   my_i2  = 0;

#pragma unroll
    for (int sel = 0; sel < 8; sel++) {
        float m = s1[0]; int mi = 0;
#pragma unroll
        for (int i = 1; i < 8; i++) if (s1[i] > m) { m = s1[i]; mi = i; }
        float bm = m; int bi = lane * 8 + mi;
#pragma unroll
        for (int off = 16; off; off >>= 1) {
            float om = __shfl_xor_sync(FULLMASK, bm, off);
            int   oi = __shfl_xor_sync(FULLMASK, bi, off);
            if (om > bm || (om == bm && oi < bi)) { bm = om; bi = oi; }
        }
        if (lane == sel) { my_sc1 = bm; my_i1 = bi; }
#pragma unroll
        for (int i = 0; i < 8; i++) if (bi == lane * 8 + i) s1[i] = -INFINITY;
    }

#pragma unroll
    for (int sel = 0; sel < 8; sel++) {
        float m = s2[0]; int mi = 0;
#pragma unroll
        for (int i = 1; i < 8; i++) if (s2[i] > m) { m = s2[i]; mi = i; }
        float bm = m; int bi = lane * 8 + mi;
#pragma unroll
        for (int off = 16; off; off >>= 1) {
            float om = __shfl_xor_sync(FULLMASK, bm, off);
            int   oi = __shfl_xor_sync(FULLMASK, bi, off);
            if (om > bm || (om == bm && oi < bi)) { bm = om; bi = oi; }
        }
        if (lane == sel) { my_sc2 = bm; my_i2 = bi; }
#pragma unroll
        for (int i = 0; i < 8; i++) if (bi == lane * 8 + i) s2[i] = -INFINITY;
    }

    // 64 combos, flat idx p = i*8 + j. Lane covers p = lane and p = lane+32.
    // sc1 part via shfl from lane (p>>3); sc2 part via shfl from lane (p&7).
    float a0 = __shfl_sync(FULLMASK, my_sc1, lane >> 3);
    float a1 = __shfl_sync(FULLMASK, my_sc1, (lane >> 3) + 4);
    float b0 = __shfl_sync(FULLMASK, my_sc2, lane & 7);
    float cv0 = a0 + b0;          // combo p = lane
    float cv1 = a1 + b0;          // combo p = lane + 32

    float my_fsc = -INFINITY; int my_fp = 0;
#pragma unroll
    for (int sel = 0; sel < 8; sel++) {
        float m; int mi;
        if (cv0 >= cv1) { m = cv0; mi = lane; } else { m = cv1; mi = lane + 32; }
        float bm = m; int bi = mi;
#pragma unroll
        for (int off = 16; off; off >>= 1) {
            float om = __shfl_xor_sync(FULLMASK, bm, off);
            int   oi = __shfl_xor_sync(FULLMASK, bi, off);
            if (om > bm || (om == bm && oi < bi)) { bm = om; bi = oi; }
        }
        if (lane == sel) { my_fsc = bm; my_fp = bi; }
        if (bi == lane)           cv0 = -INFINITY;
        else if (bi == lane + 32) cv1 = -INFINITY;
    }

    // softmax over the 8 winners (values live on lanes 0..7, descending)
    float mx = __shfl_sync(FULLMASK, my_fsc, 0);
    float e = (lane < 8) ? expf(my_fsc - mx) : 0.f;
    float sum = e;
#pragma unroll
    for (int off = 16; off; off >>= 1) sum += __shfl_xor_sync(FULLMASK, sum, off);
    float inv = 1.f / sum;

    // flat index -> (i1[p>>3], i2[p&7]) via shfl (warp-uniform execution)
    int p  = my_fp;                                  // valid on lanes 0..7
    int ia = __shfl_sync(FULLMASK, my_i1, (p >> 3) & 31);
    int ib = __shfl_sync(FULLMASK, my_i2, p & 7);

    if (lane < 8) {
        oidx[(size_t)gw * 8 + lane] = ia * NKEYS + ib;
        ow  [(size_t)gw * 8 + lane] = e * inv;
    }
}

// ---------------------------------------------------------------------------
// Kernel C: weighted gather  out[t] = sum_k w[t][k] * values[idx[t][k]]
// ---------------------------------------------------------------------------
__global__ __launch_bounds__(256) void gather_kernel(
    const int* __restrict__ oidx, const float* __restrict__ ow,
    const float* __restrict__ values, float* __restrict__ out)
{
    const int t = blockIdx.x;
    const int tid = threadIdx.x;
    __shared__ int   sidx[16];
    __shared__ float sw[16];
    if (tid < 16) {
        sidx[tid] = oidx[(size_t)t * 16 + tid];
        sw[tid]   = ow  [(size_t)t * 16 + tid];
    }
    __syncthreads();

    float4 acc = make_float4(0.f, 0.f, 0.f, 0.f);
#pragma unroll
    for (int k = 0; k < 16; k++) {
        const float4* vp = (const float4*)(values + (size_t)sidx[k] * D_IN) + tid;
        float4 v = *vp;
        float w = sw[k];
        acc.x = fmaf(w, v.x, acc.x);
        acc.y = fmaf(w, v.y, acc.y);
        acc.z = fmaf(w, v.z, acc.z);
        acc.w = fmaf(w, v.w, acc.w);
    }
    ((float4*)out)[(size_t)t * 256 + tid] = acc;
}

// ---------------------------------------------------------------------------
extern "C" void kernel_launch(void* const* d_in, const int* in_sizes, int n_in,
                              void* d_out, int out_size)
{
    const float* x      = (const float*)d_in[0];
    const float* W1     = (const float*)d_in[1];
    const float* b1     = (const float*)d_in[2];
    const float* W2     = (const float*)d_in[3];
    const float* b2     = (const float*)d_in[4];
    const float* keys   = (const float*)d_in[5];
    const float* values = (const float*)d_in[6];
    float* out = (float*)d_out;

    const int T = in_sizes[0] / D_IN;   // 8192

    float* qbuf;  cudaGetSymbolAddress((void**)&qbuf, g_q);
    int*   idxb;  cudaGetSymbolAddress((void**)&idxb, g_idx);
    float* wb;    cudaGetSymbolAddress((void**)&wb,   g_w);

    const int smemA = (64 * 130 + 128 * 32) * (int)sizeof(float);  // 49664 B
    cudaFuncSetAttribute(mlp_kernel, cudaFuncAttributeMaxDynamicSharedMemorySize, smemA);

    mlp_kernel<<<T / 64, 256, smemA>>>(x, W1, b1, W2, b2, qbuf);
    topk_kernel<<<(T * 2 * 32 + 255) / 256, 256>>>(qbuf, keys, idxb, wb, T);
    gather_kernel<<<T, 256>>>(idxb, wb, values, out);
}

// round 3
// speedup vs baseline: 2.1535x; 1.9601x over previous
#include <cuda_runtime.h>
#include <math.h>

#define D_IN  1024
#define H1    128
#define QD    32
#define NKEYS 256
#define HALF  8
#define FULLMASK 0xffffffffu

// smem layout (floats):
//   phase1: Xs [64][36] @0 (2304), Ws [32][132] @2304 (4224)  -> ends 6528
//   phase2: Hs [64][132] @0 (8448), W2s [32][129] @8448 (4128) -> ends 12576
//   qS [64][32] @12576 (2048), idxS [64][16] @14624 (1024), wS @15648 (1024)
//   total = 16672 floats = 66688 bytes
#define SM_WS    2304
#define SM_W2S   8448
#define SM_QS    12576
#define SM_IDX   14624
#define SM_W     15648
#define SM_TOTAL 16672

__global__ __launch_bounds__(512, 1) void fused_kernel(
    const float* __restrict__ x,  const float* __restrict__ W1,
    const float* __restrict__ b1, const float* __restrict__ W2,
    const float* __restrict__ b2, const float* __restrict__ keys,
    const float* __restrict__ values, float* __restrict__ out)
{
    extern __shared__ float smem[];
    float* Xs  = smem;             // [64][36]
    float* Ws  = smem + SM_WS;     // [32][132] k-major
    float* Hs  = smem;             // [64][132]
    float* W2s = smem + SM_W2S;    // [32][129] row-major (c,k)
    float* qS  = smem + SM_QS;     // [64][32]
    int*   idxS = (int*)(smem + SM_IDX);   // [64][16]
    float* wS  = smem + SM_W;      // [64][16]

    const int tid  = threadIdx.x;
    const int lane = tid & 31;
    const int wid  = tid >> 5;              // 0..15
    const int block_row = blockIdx.x * 64;

    // ---------------- Phase 1: h = relu(x @ W1^T + b1) -------------------
    const int tcol = lane * 4;              // 0..124
    const int trow = wid * 4;               // 0..60
    const int xr = tid >> 3;                // 0..63
    const int xk = (tid & 7) * 4;           // 0,4,...,28

    float acc[4][4];
#pragma unroll
    for (int r = 0; r < 4; r++)
#pragma unroll
        for (int c = 0; c < 4; c++) acc[r][c] = 0.f;

    const float* xBase = x + (size_t)block_row * D_IN;

    for (int k0 = 0; k0 < D_IN; k0 += 32) {
        float4 xv = *(const float4*)(xBase + (size_t)xr * D_IN + k0 + xk);
        float4 w0 = *(const float4*)(W1 + (size_t)xr        * D_IN + k0 + xk);
        float4 w1 = *(const float4*)(W1 + (size_t)(xr + 64) * D_IN + k0 + xk);
        __syncthreads();
        *(float4*)&Xs[xr * 36 + xk] = xv;
        Ws[(xk + 0) * 132 + xr] = w0.x;
        Ws[(xk + 1) * 132 + xr] = w0.y;
        Ws[(xk + 2) * 132 + xr] = w0.z;
        Ws[(xk + 3) * 132 + xr] = w0.w;
        Ws[(xk + 0) * 132 + xr + 64] = w1.x;
        Ws[(xk + 1) * 132 + xr + 64] = w1.y;
        Ws[(xk + 2) * 132 + xr + 64] = w1.z;
        Ws[(xk + 3) * 132 + xr + 64] = w1.w;
        __syncthreads();

#pragma unroll 8
        for (int k = 0; k < 32; k++) {
            float4 wv = *(const float4*)&Ws[k * 132 + tcol];
            float xb[4];
#pragma unroll
            for (int r = 0; r < 4; r++) xb[r] = Xs[(trow + r) * 36 + k];
#pragma unroll
            for (int r = 0; r < 4; r++) {
                acc[r][0] = fmaf(xb[r], wv.x, acc[r][0]);
                acc[r][1] = fmaf(xb[r], wv.y, acc[r][1]);
                acc[r][2] = fmaf(xb[r], wv.z, acc[r][2]);
                acc[r][3] = fmaf(xb[r], wv.w, acc[r][3]);
            }
        }
    }

    __syncthreads();   // done reading Xs/Ws; Hs overlays them

    // ---------------- Phase 2: q = relu_h @ W2^T + b2 --------------------
    {
        float4 b1v = *(const float4*)&b1[tcol];
#pragma unroll
        for (int r = 0; r < 4; r++) {
            float4 hv;
            hv.x = fmaxf(acc[r][0] + b1v.x, 0.f);
            hv.y = fmaxf(acc[r][1] + b1v.y, 0.f);
            hv.z = fmaxf(acc[r][2] + b1v.z, 0.f);
            hv.w = fmaxf(acc[r][3] + b1v.w, 0.f);
            *(float4*)&Hs[(trow + r) * 132 + tcol] = hv;
        }
        for (int i = tid; i < 32 * 128; i += 512) {
            int c = i >> 7, k = i & 127;
            W2s[c * 129 + k] = W2[i];
        }
    }
    __syncthreads();

    {
        const int rr = tid >> 3;            // 0..63
        const int cb = (tid & 7) * 4;       // 0..28
        float a2[4] = {0.f, 0.f, 0.f, 0.f};
#pragma unroll 4
        for (int k = 0; k < H1; k++) {
            float hv = Hs[rr * 132 + k];
            a2[0] = fmaf(hv, W2s[(cb + 0) * 129 + k], a2[0]);
            a2[1] = fmaf(hv, W2s[(cb + 1) * 129 + k], a2[1]);
            a2[2] = fmaf(hv, W2s[(cb + 2) * 129 + k], a2[2]);
            a2[3] = fmaf(hv, W2s[(cb + 3) * 129 + k], a2[3]);
        }
        float4 qv;
        qv.x = a2[0] + b2[cb + 0];
        qv.y = a2[1] + b2[cb + 1];
        qv.z = a2[2] + b2[cb + 2];
        qv.w = a2[3] + b2[cb + 3];
        *(float4*)&qS[rr * QD + cb] = qv;
    }
    __syncthreads();

    // ---------------- Phase 3: topk per (token, head) --------------------
    for (int task = wid; task < 128; task += 16) {
        const int tl = task >> 1, h = task & 1;
        const float* qp = &qS[tl * QD + h * 16];

        float q1[HALF], q2[HALF];
#pragma unroll
        for (int c = 0; c < HALF; c++) { q1[c] = qp[c]; q2[c] = qp[HALF + c]; }

        float s1[8], s2[8];
        {
            const float4* k1 = (const float4*)(keys + ((size_t)(h * 2 + 0) * NKEYS + lane * 8) * HALF);
            const float4* k2 = (const float4*)(keys + ((size_t)(h * 2 + 1) * NKEYS + lane * 8) * HALF);
#pragma unroll
            for (int j = 0; j < 8; j++) {
                float4 u1 = k1[j * 2], v1 = k1[j * 2 + 1];
                float4 u2 = k2[j * 2], v2 = k2[j * 2 + 1];
                float a = 0.f, b = 0.f;
                a = fmaf(q1[0], u1.x, a); a = fmaf(q1[1], u1.y, a);
                a = fmaf(q1[2], u1.z, a); a = fmaf(q1[3], u1.w, a);
                a = fmaf(q1[4], v1.x, a); a = fmaf(q1[5], v1.y, a);
                a = fmaf(q1[6], v1.z, a); a = fmaf(q1[7], v1.w, a);
                b = fmaf(q2[0], u2.x, b); b = fmaf(q2[1], u2.y, b);
                b = fmaf(q2[2], u2.z, b); b = fmaf(q2[3], u2.w, b);
                b = fmaf(q2[4], v2.x, b); b = fmaf(q2[5], v2.y, b);
                b = fmaf(q2[6], v2.z, b); b = fmaf(q2[7], v2.w, b);
                s1[j] = a; s2[j] = b;
            }
        }

        float my_sc1 = 0.f, my_sc2 = 0.f;
        int   my_i1 = 0, my_i2 = 0;

#pragma unroll
        for (int sel = 0; sel < 8; sel++) {
            float m = s1[0]; int mi = 0;
#pragma unroll
            for (int i = 1; i < 8; i++) if (s1[i] > m) { m = s1[i]; mi = i; }
            float bm = m; int bi = lane * 8 + mi;
#pragma unroll
            for (int off = 16; off; off >>= 1) {
                float om = __shfl_xor_sync(FULLMASK, bm, off);
                int   oi = __shfl_xor_sync(FULLMASK, bi, off);
                if (om > bm || (om == bm && oi < bi)) { bm = om; bi = oi; }
            }
            if (lane == sel) { my_sc1 = bm; my_i1 = bi; }
#pragma unroll
            for (int i = 0; i < 8; i++) if (bi == lane * 8 + i) s1[i] = -INFINITY;
        }

#pragma unroll
        for (int sel = 0; sel < 8; sel++) {
            float m = s2[0]; int mi = 0;
#pragma unroll
            for (int i = 1; i < 8; i++) if (s2[i] > m) { m = s2[i]; mi = i; }
            float bm = m; int bi = lane * 8 + mi;
#pragma unroll
            for (int off = 16; off; off >>= 1) {
                float om = __shfl_xor_sync(FULLMASK, bm, off);
                int   oi = __shfl_xor_sync(FULLMASK, bi, off);
                if (om > bm || (om == bm && oi < bi)) { bm = om; bi = oi; }
            }
            if (lane == sel) { my_sc2 = bm; my_i2 = bi; }
#pragma unroll
            for (int i = 0; i < 8; i++) if (bi == lane * 8 + i) s2[i] = -INFINITY;
        }

        float a0 = __shfl_sync(FULLMASK, my_sc1, lane >> 3);
        float a1 = __shfl_sync(FULLMASK, my_sc1, (lane >> 3) + 4);
        float b0 = __shfl_sync(FULLMASK, my_sc2, lane & 7);
        float cv0 = a0 + b0;
        float cv1 = a1 + b0;

        float my_fsc = -INFINITY; int my_fp = 0;
#pragma unroll
        for (int sel = 0; sel < 8; sel++) {
            float m; int mi;
            if (cv0 >= cv1) { m = cv0; mi = lane; } else { m = cv1; mi = lane + 32; }
            float bm = m; int bi = mi;
#pragma unroll
            for (int off = 16; off; off >>= 1) {
                float om = __shfl_xor_sync(FULLMASK, bm, off);
                int   oi = __shfl_xor_sync(FULLMASK, bi, off);
                if (om > bm || (om == bm && oi < bi)) { bm = om; bi = oi; }
            }
            if (lane == sel) { my_fsc = bm; my_fp = bi; }
            if (bi == lane)           cv0 = -INFINITY;
            else if (bi == lane + 32) cv1 = -INFINITY;
        }

        float mx = __shfl_sync(FULLMASK, my_fsc, 0);
        float e = expf(my_fsc - mx);           // lanes >=8 give exp(-inf)=0
        float sum = e;
#pragma unroll
        for (int off = 16; off; off >>= 1) sum += __shfl_xor_sync(FULLMASK, sum, off);
        float inv = 1.f / sum;

        int p  = my_fp;
        int ia = __shfl_sync(FULLMASK, my_i1, (p >> 3) & 31);
        int ib = __shfl_sync(FULLMASK, my_i2, p & 7);

        if (lane < 8) {
            idxS[tl * 16 + h * 8 + lane] = ia * NKEYS + ib;
            wS  [tl * 16 + h * 8 + lane] = e * inv;
        }
    }
    __syncthreads();

    // ---------------- Phase 4: gather ------------------------------------
    {
        const int g = tid >> 8;        // 0/1
        const int t2 = tid & 255;
        for (int tl = g; tl < 64; tl += 2) {
            float4 acc4 = make_float4(0.f, 0.f, 0.f, 0.f);
#pragma unroll
            for (int k = 0; k < 16; k++) {
                int   idx = idxS[tl * 16 + k];
                float w   = wS [tl * 16 + k];
                float4 v = ((const float4*)(values + ((size_t)idx << 10)))[t2];
                acc4.x = fmaf(w, v.x, acc4.x);
                acc4.y = fmaf(w, v.y, acc4.y);
                acc4.z = fmaf(w, v.z, acc4.z);
                acc4.w = fmaf(w, v.w, acc4.w);
            }
            ((float4*)(out + ((size_t)(block_row + tl) << 10)))[t2] = acc4;
        }
    }
}

extern "C" void kernel_launch(void* const* d_in, const int* in_sizes, int n_in,
                              void* d_out, int out_size)
{
    const float* x      = (const float*)d_in[0];
    const float* W1     = (const float*)d_in[1];
    const float* b1     = (const float*)d_in[2];
    const float* W2     = (const float*)d_in[3];
    const float* b2     = (const float*)d_in[4];
    const float* keys   = (const float*)d_in[5];
    const float* values = (const float*)d_in[6];
    float* out = (float*)d_out;

    const int T = in_sizes[0] / D_IN;   // 8192
    const int smemB = SM_TOTAL * (int)sizeof(float);  // 66688

    static int configured = -1;
    if (configured < 0) {
        cudaFuncSetAttribute(fused_kernel,
                             cudaFuncAttributeMaxDynamicSharedMemorySize, smemB);
        configured = 1;
    }

    fused_kernel<<<T / 64, 512, smemB>>>(x, W1, b1, W2, b2, keys, values, out);
}

// round 4
// speedup vs baseline: 2.1722x; 1.0087x over previous
#include <cuda_runtime.h>
#include <math.h>

#define D_IN  1024
#define H1    128
#define QD    32
#define NKEYS 256
#define HALF  8
#define FULLMASK 0xffffffffu

// smem layout (floats), BM=32:
//   phase1: Xs [32][36] @0 (1152), Ws [32][132] @1152+? -> put Ws @1152 (4224) ends 5376
//   phase2: Hs [32][132] @0 (4224), W2s [32][129] @4224 (4128) ends 8352
//   qS [32][32] @8352 (1024), idxS [32][16] @9376 (512), wS @9888 (512)
//   total = 10400 floats = 41600 bytes
#define SM_WS    1152
#define SM_W2S   4224
#define SM_QS    8352
#define SM_IDX   9376
#define SM_W     9888
#define SM_TOTAL 10400

__global__ __launch_bounds__(256, 2) void fused_kernel(
    const float* __restrict__ x,  const float* __restrict__ W1,
    const float* __restrict__ b1, const float* __restrict__ W2,
    const float* __restrict__ b2, const float* __restrict__ keys,
    const float* __restrict__ values, float* __restrict__ out)
{
    extern __shared__ float smem[];
    float* Xs  = smem;             // [32][36]
    float* Ws  = smem + SM_WS;     // [32][132] k-major
    float* Hs  = smem;             // [32][132]
    float* W2s = smem + SM_W2S;    // [32][129] row-major (c,k)
    float* qS  = smem + SM_QS;     // [32][32]
    int*   idxS = (int*)(smem + SM_IDX);   // [32][16]
    float* wS  = smem + SM_W;      // [32][16]

    const int tid  = threadIdx.x;
    const int lane = tid & 31;
    const int wid  = tid >> 5;              // 0..7
    const int block_row = blockIdx.x * 32;

    // ---------------- Phase 1: h = relu(x @ W1^T + b1) -------------------
    const int tcol = lane * 4;              // 0..124
    const int trow = wid * 4;               // 0..28
    const int xr = tid >> 3;                // 0..31
    const int xk = (tid & 7) * 4;           // 0..28

    float acc[4][4];
#pragma unroll
    for (int r = 0; r < 4; r++)
#pragma unroll
        for (int c = 0; c < 4; c++) acc[r][c] = 0.f;

    const float* xBase = x + (size_t)block_row * D_IN;

    for (int k0 = 0; k0 < D_IN; k0 += 32) {
        // X tile: 32x32 = 256 float4, one per thread
        float4 xv = *(const float4*)(xBase + (size_t)xr * D_IN + k0 + xk);
        // W1 tile: 128 rows x 32 cols = 1024 float4, 4 per thread
        float4 wv[4];
#pragma unroll
        for (int i = 0; i < 4; i++) {
            int j = tid + i * 256;
            int n = j >> 3, kq = (j & 7) * 4;
            wv[i] = *(const float4*)(W1 + (size_t)n * D_IN + k0 + kq);
        }
        __syncthreads();
        *(float4*)&Xs[xr * 36 + xk] = xv;
#pragma unroll
        for (int i = 0; i < 4; i++) {
            int j = tid + i * 256;
            int n = j >> 3, kq = (j & 7) * 4;
            Ws[(kq + 0) * 132 + n] = wv[i].x;
            Ws[(kq + 1) * 132 + n] = wv[i].y;
            Ws[(kq + 2) * 132 + n] = wv[i].z;
            Ws[(kq + 3) * 132 + n] = wv[i].w;
        }
        __syncthreads();

#pragma unroll 8
        for (int k = 0; k < 32; k++) {
            float4 w4 = *(const float4*)&Ws[k * 132 + tcol];
            float xb[4];
#pragma unroll
            for (int r = 0; r < 4; r++) xb[r] = Xs[(trow + r) * 36 + k];
#pragma unroll
            for (int r = 0; r < 4; r++) {
                acc[r][0] = fmaf(xb[r], w4.x, acc[r][0]);
                acc[r][1] = fmaf(xb[r], w4.y, acc[r][1]);
                acc[r][2] = fmaf(xb[r], w4.z, acc[r][2]);
                acc[r][3] = fmaf(xb[r], w4.w, acc[r][3]);
            }
        }
    }

    __syncthreads();   // done reading Xs/Ws; Hs overlays them

    // ---------------- Phase 2: q = relu_h @ W2^T + b2 --------------------
    {
        float4 b1v = *(const float4*)&b1[tcol];
#pragma unroll
        for (int r = 0; r < 4; r++) {
            float4 hv;
            hv.x = fmaxf(acc[r][0] + b1v.x, 0.f);
            hv.y = fmaxf(acc[r][1] + b1v.y, 0.f);
            hv.z = fmaxf(acc[r][2] + b1v.z, 0.f);
            hv.w = fmaxf(acc[r][3] + b1v.w, 0.f);
            *(float4*)&Hs[(trow + r) * 132 + tcol] = hv;
        }
        // W2 [32][128] -> W2s [c][k] stride 129
        for (int i = tid; i < 32 * 128; i += 256) {
            int c = i >> 7, k = i & 127;
            W2s[c * 129 + k] = W2[i];
        }
    }
    __syncthreads();

    {
        const int rr = tid >> 3;            // 0..31
        const int cb = (tid & 7) * 4;       // 0..28
        float a2[4] = {0.f, 0.f, 0.f, 0.f};
#pragma unroll 4
        for (int k = 0; k < H1; k++) {
            float hv = Hs[rr * 132 + k];
            a2[0] = fmaf(hv, W2s[(cb + 0) * 129 + k], a2[0]);
            a2[1] = fmaf(hv, W2s[(cb + 1) * 129 + k], a2[1]);
            a2[2] = fmaf(hv, W2s[(cb + 2) * 129 + k], a2[2]);
            a2[3] = fmaf(hv, W2s[(cb + 3) * 129 + k], a2[3]);
        }
        float4 qv;
        qv.x = a2[0] + b2[cb + 0];
        qv.y = a2[1] + b2[cb + 1];
        qv.z = a2[2] + b2[cb + 2];
        qv.w = a2[3] + b2[cb + 3];
        *(float4*)&qS[rr * QD + cb] = qv;
    }
    __syncthreads();

    // ---------------- Phase 3: topk per (token, head) --------------------
    for (int task = wid; task < 64; task += 8) {
        const int tl = task >> 1, h = task & 1;
        const float* qp = &qS[tl * QD + h * 16];

        float q1[HALF], q2[HALF];
#pragma unroll
        for (int c = 0; c < HALF; c++) { q1[c] = qp[c]; q2[c] = qp[HALF + c]; }

        float s1[8], s2[8];
        {
            const float4* k1 = (const float4*)(keys + ((size_t)(h * 2 + 0) * NKEYS + lane * 8) * HALF);
            const float4* k2 = (const float4*)(keys + ((size_t)(h * 2 + 1) * NKEYS + lane * 8) * HALF);
#pragma unroll
            for (int j = 0; j < 8; j++) {
                float4 u1 = k1[j * 2], v1 = k1[j * 2 + 1];
                float4 u2 = k2[j * 2], v2 = k2[j * 2 + 1];
                float a = 0.f, b = 0.f;
                a = fmaf(q1[0], u1.x, a); a = fmaf(q1[1], u1.y, a);
                a = fmaf(q1[2], u1.z, a); a = fmaf(q1[3], u1.w, a);
                a = fmaf(q1[4], v1.x, a); a = fmaf(q1[5], v1.y, a);
                a = fmaf(q1[6], v1.z, a); a = fmaf(q1[7], v1.w, a);
                b = fmaf(q2[0], u2.x, b); b = fmaf(q2[1], u2.y, b);
                b = fmaf(q2[2], u2.z, b); b = fmaf(q2[3], u2.w, b);
                b = fmaf(q2[4], v2.x, b); b = fmaf(q2[5], v2.y, b);
                b = fmaf(q2[6], v2.z, b); b = fmaf(q2[7], v2.w, b);
                s1[j] = a; s2[j] = b;
            }
        }

        float my_sc1 = 0.f, my_sc2 = 0.f;
        int   my_i1 = 0, my_i2 = 0;

#pragma unroll
        for (int sel = 0; sel < 8; sel++) {
            float m = s1[0]; int mi = 0;
#pragma unroll
            for (int i = 1; i < 8; i++) if (s1[i] > m) { m = s1[i]; mi = i; }
            float bm = m; int bi = lane * 8 + mi;
#pragma unroll
            for (int off = 16; off; off >>= 1) {
                float om = __shfl_xor_sync(FULLMASK, bm, off);
                int   oi = __shfl_xor_sync(FULLMASK, bi, off);
                if (om > bm || (om == bm && oi < bi)) { bm = om; bi = oi; }
            }
            if (lane == sel) { my_sc1 = bm; my_i1 = bi; }
#pragma unroll
            for (int i = 0; i < 8; i++) if (bi == lane * 8 + i) s1[i] = -INFINITY;
        }

#pragma unroll
        for (int sel = 0; sel < 8; sel++) {
            float m = s2[0]; int mi = 0;
#pragma unroll
            for (int i = 1; i < 8; i++) if (s2[i] > m) { m = s2[i]; mi = i; }
            float bm = m; int bi = lane * 8 + mi;
#pragma unroll
            for (int off = 16; off; off >>= 1) {
                float om = __shfl_xor_sync(FULLMASK, bm, off);
                int   oi = __shfl_xor_sync(FULLMASK, bi, off);
                if (om > bm || (om == bm && oi < bi)) { bm = om; bi = oi; }
            }
            if (lane == sel) { my_sc2 = bm; my_i2 = bi; }
#pragma unroll
            for (int i = 0; i < 8; i++) if (bi == lane * 8 + i) s2[i] = -INFINITY;
        }

        float a0 = __shfl_sync(FULLMASK, my_sc1, lane >> 3);
        float a1 = __shfl_sync(FULLMASK, my_sc1, (lane >> 3) + 4);
        float b0 = __shfl_sync(FULLMASK, my_sc2, lane & 7);
        float cv0 = a0 + b0;
        float cv1 = a1 + b0;

        float my_fsc = -INFINITY; int my_fp = 0;
#pragma unroll
        for (int sel = 0; sel < 8; sel++) {
            float m; int mi;
            if (cv0 >= cv1) { m = cv0; mi = lane; } else { m = cv1; mi = lane + 32; }
            float bm = m; int bi = mi;
#pragma unroll
            for (int off = 16; off; off >>= 1) {
                float om = __shfl_xor_sync(FULLMASK, bm, off);
                int   oi = __shfl_xor_sync(FULLMASK, bi, off);
                if (om > bm || (om == bm && oi < bi)) { bm = om; bi = oi; }
            }
            if (lane == sel) { my_fsc = bm; my_fp = bi; }
            if (bi == lane)           cv0 = -INFINITY;
            else if (bi == lane + 32) cv1 = -INFINITY;
        }

        float mx = __shfl_sync(FULLMASK, my_fsc, 0);
        float e = expf(my_fsc - mx);
        float sum = e;
#pragma unroll
        for (int off = 16; off; off >>= 1) sum += __shfl_xor_sync(FULLMASK, sum, off);
        float inv = 1.f / sum;

        int p  = my_fp;
        int ia = __shfl_sync(FULLMASK, my_i1, (p >> 3) & 31);
        int ib = __shfl_sync(FULLMASK, my_i2, p & 7);

        if (lane < 8) {
            idxS[tl * 16 + h * 8 + lane] = ia * NKEYS + ib;
            wS  [tl * 16 + h * 8 + lane] = e * inv;
        }
    }
    __syncthreads();

    // ---------------- Phase 4: gather ------------------------------------
    {
        for (int tl = 0; tl < 32; tl++) {
            float4 acc4 = make_float4(0.f, 0.f, 0.f, 0.f);
#pragma unroll
            for (int k = 0; k < 16; k++) {
                int   idx = idxS[tl * 16 + k];
                float w   = wS [tl * 16 + k];
                float4 v = ((const float4*)(values + ((size_t)idx << 10)))[tid];
                acc4.x = fmaf(w, v.x, acc4.x);
                acc4.y = fmaf(w, v.y, acc4.y);
                acc4.z = fmaf(w, v.z, acc4.z);
                acc4.w = fmaf(w, v.w, acc4.w);
            }
            ((float4*)(out + ((size_t)(block_row + tl) << 10)))[tid] = acc4;
        }
    }
}

extern "C" void kernel_launch(void* const* d_in, const int* in_sizes, int n_in,
                              void* d_out, int out_size)
{
    const float* x      = (const float*)d_in[0];
    const float* W1     = (const float*)d_in[1];
    const float* b1     = (const float*)d_in[2];
    const float* W2     = (const float*)d_in[3];
    const float* b2     = (const float*)d_in[4];
    const float* keys   = (const float*)d_in[5];
    const float* values = (const float*)d_in[6];
    float* out = (float*)d_out;

    const int T = in_sizes[0] / D_IN;   // 8192
    const int smemB = SM_TOTAL * (int)sizeof(float);  // 41600

    cudaFuncSetAttribute(fused_kernel,
                         cudaFuncAttributeMaxDynamicSharedMemorySize, smemB);

    fused_kernel<<<T / 32, 256, smemB>>>(x, W1, b1, W2, b2, keys, values, out);
}